// round 14
// baseline (speedup 1.0000x reference)
#include <cuda_runtime.h>
#include <cuda_fp16.h>

#define MDIM 1024
#define GR   32                 // rows per block = 8 warps x 4 rows (2 half2 pairs)
#define TPB  256

typedef unsigned int u32;

// pair buffer: x[0,1024) | plus[1024,2048) | prod[2048,3072) in half2 words.
// stride 12352 B = 3088 words (== 16 mod 32 banks; 16B aligned) so the two
// pairs of a warp are bank-staggered by 16 -> half-A and half-B contiguous
// stores/gathers never structurally collide.
#define PAIR_BYTES   12352
#define WARP_BYTES   (2*PAIR_BYTES)            // 24704
#define BUF_BYTES    (8*WARP_BYTES)            // 197632
#define SIDX_OFF     (BUF_BYTES)               // short4[M] remapped parents     8192
#define SWAB_OFF     (SIDX_OFF + MDIM*8)       // uint2[M] (w0x2,w1x2) half2 bc  8192
#define SBB_OFF      (SWAB_OFF + MDIM*8)       // u32[M]   (bx2) half2 bc        4096
#define WEPI_OFF     (SBB_OFF  + MDIM*4)       // float2[M] (wp',wq') permuted   8192
#define OFFS_OFF     (WEPI_OFF + MDIM*8)       // short[1026] level offsets      2056
#define SMEM_BYTES   (OFFS_OFF + 2056)         // 228360 <= 232448 cap

__device__ __forceinline__ __half2 tanh2_approx(__half2 v) {
    u32 u = *reinterpret_cast<u32*>(&v);
    u32 r;
    asm("tanh.approx.f16x2 %0, %1;" : "=r"(r) : "r"(u));
    return *reinterpret_cast<__half2*>(&r);
}

// ---------------------------------------------------------------------------
// Fused kernel: 4 rows per warp. Lanes 0-15 process the level schedule for
// pair A, lanes 16-31 the SAME steps for pair B (schedule loads broadcast).
// Mean level width ~12 <= 16, so formerly idle lanes now carry rows; per-row
// issue cost halves. All math f16x2 (2 rows per op): sigmoid via
// tanh.approx.f16x2 with weights pre-halved; prod via HMUL2. Setup (exact DAG
// levels, counting sort, remap: enc(x,c)=c, enc(plus,s)=1024+pos,
// enc(prod,s)=2048+pos in half2 words) is block-local as before.
// ---------------------------------------------------------------------------
__global__ void __launch_bounds__(TPB, 1)
tree_kernel(const float* __restrict__ x,      const int* __restrict__ raw,
            const float* __restrict__ W_base, const float* __restrict__ b_base,
            const float* __restrict__ W_sig,  const float* __restrict__ b_sig,
            const float* __restrict__ w_plus, const float* __restrict__ b_plus,
            const float* __restrict__ w_prod, const float* __restrict__ b_prod,
            float* __restrict__ out, int nGroups)
{
    extern __shared__ char smraw[];
    short4*  sIdx = (short4*)(smraw + SIDX_OFF);
    uint2*   sWab = (uint2*) (smraw + SWAB_OFF);
    u32*     sBb  = (u32*)   (smraw + SBB_OFF);
    float2*  wepi = (float2*)(smraw + WEPI_OFF);
    short*   offs = (short*) (smraw + OFFS_OFF);

    // setup scratch overlaid on buffer region (released before staging rows)
    short4* sP   = (short4*)smraw;                       // [M] raw parents
    int*    lvl  = (int*)(smraw + 8192);
    int*    cnt  = (int*)(smraw + 12288);
    int*    cur  = (int*)(smraw + 16384);
    int*    posA = (int*)(smraw + 20480);

    int tid  = threadIdx.x;
    int lane = tid & 31;
    int wid  = tid >> 5;

    // ---- Phase 0: stage parents, zero counters ----------------------------
    for (int i = tid; i < MDIM; i += TPB) {
        short4 p;
        p.x = (short)raw[2*i];          p.y = (short)raw[2*i + 1];
        p.z = (short)raw[2*MDIM + 2*i]; p.w = (short)raw[2*MDIM + 2*i + 1];
        sP[i] = p;
        cnt[i] = 0;
    }
    __syncthreads();

    // ---- Phase 1: exact DAG levels, warp 0 over 32-step chunks ------------
    if (wid == 0) {
        for (int c = 0; c < MDIM/32; c++) {
            int idx  = c*32 + lane;
            int base = c*32;
            short4 p = sP[idx];
            int l = 0;
            int e0 = -1, e1 = -1, e2 = -1, e3 = -1;
            int q;
            q = p.x; if (q >= MDIM) { int pc = q & (MDIM-1); if (pc < base) l = max(l, lvl[pc]+1); else e0 = pc - base; }
            q = p.y; if (q >= MDIM) { int pc = q & (MDIM-1); if (pc < base) l = max(l, lvl[pc]+1); else e1 = pc - base; }
            q = p.z; if (q >= MDIM) { int pc = q & (MDIM-1); if (pc < base) l = max(l, lvl[pc]+1); else e2 = pc - base; }
            q = p.w; if (q >= MDIM) { int pc = q & (MDIM-1); if (pc < base) l = max(l, lvl[pc]+1); else e3 = pc - base; }
            for (;;) {
                int v0 = __shfl_sync(0xffffffffu, l, e0 < 0 ? 0 : e0);
                int v1 = __shfl_sync(0xffffffffu, l, e1 < 0 ? 0 : e1);
                int v2 = __shfl_sync(0xffffffffu, l, e2 < 0 ? 0 : e2);
                int v3 = __shfl_sync(0xffffffffu, l, e3 < 0 ? 0 : e3);
                int nl = l;
                if (e0 >= 0) nl = max(nl, v0 + 1);
                if (e1 >= 0) nl = max(nl, v1 + 1);
                if (e2 >= 0) nl = max(nl, v2 + 1);
                if (e3 >= 0) nl = max(nl, v3 + 1);
                unsigned ch = __ballot_sync(0xffffffffu, nl != l);
                l = nl;
                if (!ch) break;
            }
            lvl[idx] = l;
        }
    }
    __syncthreads();

    // ---- Phase 2: level histogram -----------------------------------------
    for (int i = tid; i < MDIM; i += TPB) atomicAdd(&cnt[lvl[i]], 1);
    __syncthreads();

    // ---- Phase 3: warp-0 scan -> level offsets ----------------------------
    if (wid == 0) {
        int carry = 0;
        for (int b = 0; b < MDIM; b += 32) {
            int v = cnt[b + lane];
            int s = v;
            #pragma unroll
            for (int o = 1; o < 32; o <<= 1) {
                int t = __shfl_up_sync(0xffffffffu, s, o);
                if (lane >= o) s += t;
            }
            int excl = carry + s - v;
            offs[b + lane] = (short)excl;
            cur[b + lane]  = excl;
            carry += __shfl_sync(0xffffffffu, s, 31);
        }
        if (lane == 0) { offs[MDIM] = MDIM; offs[MDIM+1] = MDIM; }
    }
    __syncthreads();

    // ---- Phase 4: schedule position of every step (block-local perm) ------
    for (int i = tid; i < MDIM; i += TPB) posA[i] = atomicAdd(&cur[lvl[i]], 1);
    __syncthreads();

    // ---- Phase 5: emit remapped packed schedule ---------------------------
    // enc in half2 words: x -> c ; plus(s) -> 1024+pos ; prod(s) -> 2048+pos
    for (int i = tid; i < MDIM; i += TPB) {
        short4 p = sP[i];
        int pos = posA[i];
        short4 v;
        int q;
        q = p.x; v.x = (short)(q < MDIM ? q : (q < 2*MDIM ? MDIM + posA[q - MDIM] : 2*MDIM + posA[q - 2*MDIM]));
        q = p.y; v.y = (short)(q < MDIM ? q : (q < 2*MDIM ? MDIM + posA[q - MDIM] : 2*MDIM + posA[q - 2*MDIM]));
        q = p.z; v.z = (short)(q < MDIM ? q : (q < 2*MDIM ? MDIM + posA[q - MDIM] : 2*MDIM + posA[q - 2*MDIM]));
        q = p.w; v.w = (short)(q < MDIM ? q : (q < 2*MDIM ? MDIM + posA[q - MDIM] : 2*MDIM + posA[q - 2*MDIM]));
        sIdx[pos] = v;
        __half2 h0 = __float2half2_rn(W_sig[2*i]     * 0.5f);
        __half2 h1 = __float2half2_rn(W_sig[2*i + 1] * 0.5f);
        __half2 hb = __float2half2_rn(b_sig[i]       * 0.5f);
        uint2 wab;
        wab.x = *reinterpret_cast<u32*>(&h0);
        wab.y = *reinterpret_cast<u32*>(&h1);
        sWab[pos] = wab;
        sBb[pos]  = *reinterpret_cast<u32*>(&hb);
        wepi[pos] = make_float2(w_plus[i], w_prod[i]);
    }
    __syncthreads();                     // last block-wide barrier

    // ---- Main: one warp per 4 rows (2 half2 pairs), persistent ------------
    int h  = lane & 15;                  // lane within half-warp
    int ps = lane >> 4;                  // pair select (0 = A, 1 = B)
    char*    pbC = smraw + wid * WARP_BYTES + ps * PAIR_BYTES;
    __half2* pb  = (__half2*)pbC;
    float bias = b_base[0] + b_plus[0] + b_prod[0];
    const __half2 H05 = __floats2half2_rn(0.5f, 0.5f);

    for (int grp = blockIdx.x; grp < nGroups; grp += gridDim.x) {
        // rows for this half-warp's pair
        int rowA = grp * GR + wid * 4 + ps * 2;

        // stage pair rows (fp32 coalesced per half-warp), pack half2,
        // fold x . W_base in fp32 on the fly
        const float4* xrA = (const float4*)(x + (size_t)rowA * MDIM);
        const float4* xrB = (const float4*)(x + (size_t)(rowA + 1) * MDIM);
        const float4* wb4 = (const float4*)W_base;
        float accA = 0.f, accB = 0.f;
        #pragma unroll
        for (int j = 0; j < 16; j++) {
            int p4 = j*16 + h;                  // float4 index 0..255
            float4 a  = xrA[p4];
            float4 b  = xrB[p4];
            float4 wv = wb4[p4];
            __half2 hh[4];
            hh[0] = __floats2half2_rn(a.x, b.x);
            hh[1] = __floats2half2_rn(a.y, b.y);
            hh[2] = __floats2half2_rn(a.z, b.z);
            hh[3] = __floats2half2_rn(a.w, b.w);
            ((uint4*)pb)[p4] = *(const uint4*)hh;
            accA = fmaf(a.x, wv.x, fmaf(a.y, wv.y, fmaf(a.z, wv.z, fmaf(a.w, wv.w, accA))));
            accB = fmaf(b.x, wv.x, fmaf(b.y, wv.y, fmaf(b.z, wv.z, fmaf(b.w, wv.w, accB))));
        }
        __syncwarp();

        // level loop: halves execute the same steps on their own pair;
        // schedule loads broadcast across halves; prefetch+unpack pre-sync.
        int s0 = 0;
        int s1 = (int)offs[1];
        int ix, iy, iz, iw; __half2 w0x2, w1x2, bx2;
        if (h < s1) {
            short4 q = sIdx[h];
            uint2  wab = sWab[h];
            u32    bw  = sBb[h];
            ix = q.x; iy = q.y; iz = q.z; iw = q.w;
            w0x2 = *reinterpret_cast<__half2*>(&wab.x);
            w1x2 = *reinterpret_cast<__half2*>(&wab.y);
            bx2  = *reinterpret_cast<__half2*>(&bw);
        }

        for (int L = 0; s0 < MDIM; L++) {
            int s2 = (int)offs[L + 2];
            int n = s1 - s0;
            if (h < n) {                          // chunk 0 (prefetched)
                __half2 a0 = pb[ix], a1 = pb[iy];
                __half2 m0 = pb[iz], m1 = pb[iw];
                __half2 z  = __hfma2(w0x2, a0, __hfma2(w1x2, a1, bx2));
                __half2 th = tanh2_approx(z);
                pb[2048 + s0 + h] = __hmul2(m0, m1);        // prod
                pb[1024 + s0 + h] = __hfma2(th, H05, H05);  // plus
            }
            for (int cb = s0 + 16; cb < s1; cb += 16) {     // wide-level spill
                int sp = cb + h;
                if (sp < s1) {
                    short4 q2 = sIdx[sp];
                    uint2  wab2 = sWab[sp];
                    u32    bw2  = sBb[sp];
                    __half2 a0 = pb[q2.x], a1 = pb[q2.y];
                    __half2 m0 = pb[q2.z], m1 = pb[q2.w];
                    __half2 z  = __hfma2(*reinterpret_cast<__half2*>(&wab2.x), a0,
                                 __hfma2(*reinterpret_cast<__half2*>(&wab2.y), a1,
                                         *reinterpret_cast<__half2*>(&bw2)));
                    __half2 th = tanh2_approx(z);
                    pb[2048 + sp] = __hmul2(m0, m1);
                    pb[1024 + sp] = __hfma2(th, H05, H05);
                }
            }
            {   // prefetch + unpack next level chunk 0 (pre-sync, off chain)
                int sp = s1 + h;
                if (sp < s2) {
                    short4 q = sIdx[sp];
                    uint2  wab = sWab[sp];
                    u32    bw  = sBb[sp];
                    ix = q.x; iy = q.y; iz = q.z; iw = q.w;
                    w0x2 = *reinterpret_cast<__half2*>(&wab.x);
                    w1x2 = *reinterpret_cast<__half2*>(&wab.y);
                    bx2  = *reinterpret_cast<__half2*>(&bw);
                }
            }
            __syncwarp();
            s0 = s1; s1 = s2;
        }

        // epilogue: each half-warp reduces its pair (stride-16 per half)
        for (int m = h; m < MDIM; m += 16) {
            float2 pl = __half22float2(pb[1024 + m]);
            float2 pr = __half22float2(pb[2048 + m]);
            float2 we = wepi[m];
            accA = fmaf(pl.x, we.x, fmaf(pr.x, we.y, accA));
            accB = fmaf(pl.y, we.x, fmaf(pr.y, we.y, accB));
        }
        #pragma unroll
        for (int o = 8; o; o >>= 1) {            // reduce within 16-lane half
            accA += __shfl_xor_sync(0xffffffffu, accA, o);
            accB += __shfl_xor_sync(0xffffffffu, accB, o);
        }
        if (h == 0) {
            out[rowA]     = accA + bias;
            out[rowA + 1] = accB + bias;
        }
        __syncwarp();
    }
}

// ---------------------------------------------------------------------------
extern "C" void kernel_launch(void* const* d_in, const int* in_sizes, int n_in,
                              void* d_out, int out_size) {
    const float* x  = (const float*)d_in[0];
    const int*   ri = (const int*)  d_in[1];
    const float* Wb = (const float*)d_in[2];
    const float* bb = (const float*)d_in[3];
    const float* Ws = (const float*)d_in[4];
    const float* bs = (const float*)d_in[5];
    const float* wp = (const float*)d_in[6];
    const float* bp = (const float*)d_in[7];
    const float* wq = (const float*)d_in[8];
    const float* bq = (const float*)d_in[9];
    float* out = (float*)d_out;

    int B = in_sizes[0] / MDIM;          // 8192
    int nGroups = B / GR;                // 256

    static int sm_count = 0;
    if (sm_count == 0) {
        int dev = 0;
        cudaGetDevice(&dev);
        cudaDeviceGetAttribute(&sm_count, cudaDevAttrMultiProcessorCount, dev);
        if (sm_count <= 0) sm_count = 148;
        cudaFuncSetAttribute(tree_kernel,
                             cudaFuncAttributeMaxDynamicSharedMemorySize, SMEM_BYTES);
    }
    int grid = nGroups < sm_count ? nGroups : sm_count;

    tree_kernel<<<grid, TPB, SMEM_BYTES>>>(x, ri, Wb, bb, Ws, bs, wp, bp, wq, bq,
                                           out, nGroups);
}